// round 3
// baseline (speedup 1.0000x reference)
#include <cuda_runtime.h>

#define BATCH 4
#define SEQ   2048
#define DIM   2048
#define HEADS 16
#define DHEAD 128

// Scratch (allocation-free rule: __device__ globals)
__device__ float d_qh[BATCH * SEQ * DIM];     // projected Q, [B,S,H*DH]
__device__ float d_kh[BATCH * SEQ * DHEAD];   // projected shared K head
__device__ float d_vh[BATCH * SEQ * DHEAD];   // projected shared V head
__device__ float d_ao[BATCH * SEQ * DIM];     // attention output, merged heads

// ---------------------------------------------------------------------------
// Tiled SGEMM with bias: C[M,N] = A[M,K] @ W[K,N] + bias[N]
// 256 threads, thread tile TM x TN. Requires M%BM==0, N%BN==0, K%BK==0.
// ---------------------------------------------------------------------------
template <int BM, int BN, int BK, int TM, int TN>
__global__ void __launch_bounds__(256)
gemm_bias(const float* __restrict__ A, const float* __restrict__ W,
          const float* __restrict__ bias, float* __restrict__ C,
          int M, int N, int K)
{
    __shared__ float As[BK][BM + 4];   // +4 pad: STS 2-way instead of 4-way
    __shared__ float Ws[BK][BN];

    const int tid = threadIdx.x;
    const int nx  = BN / TN;
    const int tx  = tid % nx;
    const int ty  = tid / nx;
    const int bm  = blockIdx.y * BM;
    const int bn  = blockIdx.x * BN;

    float acc[TM][TN];
#pragma unroll
    for (int i = 0; i < TM; i++)
#pragma unroll
        for (int j = 0; j < TN; j++) acc[i][j] = 0.0f;

    for (int kt = 0; kt < K; kt += BK) {
        // Load A tile (BM x BK), store transposed As[k][m]
        for (int i = tid * 4; i < BM * BK; i += 256 * 4) {
            int r = i / BK, c = i % BK;   // c in {0,4,8,12}
            float4 v = *(const float4*)(A + (long)(bm + r) * K + kt + c);
            As[c + 0][r] = v.x; As[c + 1][r] = v.y;
            As[c + 2][r] = v.z; As[c + 3][r] = v.w;
        }
        // Load W tile (BK x BN)
        for (int i = tid * 4; i < BK * BN; i += 256 * 4) {
            int r = i / BN, c = i % BN;
            *(float4*)&Ws[r][c] = *(const float4*)(W + (long)(kt + r) * N + bn + c);
        }
        __syncthreads();

#pragma unroll
        for (int k = 0; k < BK; k++) {
            float a[TM], b[TN];
#pragma unroll
            for (int i = 0; i < TM; i += 4)
                *(float4*)&a[i] = *(const float4*)&As[k][ty * TM + i];
#pragma unroll
            for (int j = 0; j < TN; j += 4)
                *(float4*)&b[j] = *(const float4*)&Ws[k][tx * TN + j];
#pragma unroll
            for (int i = 0; i < TM; i++)
#pragma unroll
                for (int j = 0; j < TN; j++)
                    acc[i][j] = fmaf(a[i], b[j], acc[i][j]);
        }
        __syncthreads();
    }

#pragma unroll
    for (int i = 0; i < TM; i++) {
        const int row = bm + ty * TM + i;
#pragma unroll
        for (int j = 0; j < TN; j += 4) {
            const int col = bn + tx * TN + j;
            float4 bb = *(const float4*)(bias + col);
            float4 o;
            o.x = acc[i][j + 0] + bb.x;
            o.y = acc[i][j + 1] + bb.y;
            o.z = acc[i][j + 2] + bb.z;
            o.w = acc[i][j + 3] + bb.w;
            *(float4*)(C + (long)row * N + col) = o;
        }
    }
}

// ---------------------------------------------------------------------------
// Flash attention for MQA.
// Qh: [B,S,H*DH] (head h = cols h*DH..), Kh/Vh: [B,S,DH] shared head.
// Out: [B,S,H*DH] merged heads. grid = (S/64, H, B), 256 threads.
// Online softmax; Ks tile XOR-swizzled (column-access ≤2-way conflict),
// Vs plain (row-access conflict-free).
// ---------------------------------------------------------------------------
__device__ __forceinline__ int kswz(int r, int c) {
    // c is a multiple of 4; 16B-chunk index XOR'ed with (row>>2)&7
    int cc = (c >> 2) ^ ((r >> 2) & 7);
    return r * 128 + (cc << 2);
}

__global__ void __launch_bounds__(256)
mqa_flash(const float* __restrict__ Qh, const float* __restrict__ Kh,
          const float* __restrict__ Vh, float* __restrict__ O)
{
    extern __shared__ float sm[];
    float* Qs = sm;                 // [64][128] plain (reads are broadcast)
    float* Ks = Qs + 64 * 128;      // [64][128] swizzled
    float* Vs = Ks + 64 * 128;      // [64][128] plain
    float* Ps = Vs + 64 * 128;      // [64][68]

    const int tid = threadIdx.x;
    const int tx  = tid & 15;
    const int ty  = tid >> 4;
    const int b   = blockIdx.z;
    const int h   = blockIdx.y;
    const int q0  = blockIdx.x * 64;
    const float scale = 0.088388347648318447f;   // 1/sqrt(128)

    // Load and pre-scale Q tile [64][128]
    const float* Qg = Qh + ((long)b * SEQ + q0) * DIM + h * DHEAD;
    for (int i = tid * 4; i < 64 * DHEAD; i += 1024) {
        int r = i >> 7, c = i & 127;
        float4 v = *(const float4*)(Qg + (long)r * DIM + c);
        v.x *= scale; v.y *= scale; v.z *= scale; v.w *= scale;
        *(float4*)&Qs[r * 128 + c] = v;
    }

    float m[4], l[4], o[4][8];
#pragma unroll
    for (int i = 0; i < 4; i++) {
        m[i] = -3.0e38f;
        l[i] = 0.0f;
#pragma unroll
        for (int j = 0; j < 8; j++) o[i][j] = 0.0f;
    }

    const float* Kg = Kh + (long)b * SEQ * DHEAD;
    const float* Vg = Vh + (long)b * SEQ * DHEAD;

    for (int j0 = 0; j0 < SEQ; j0 += 64) {
        __syncthreads();   // protect Ks/Vs/Ps readers from previous iter (and Qs on iter 0)
        // Load K (swizzled) and V (plain) tiles [64][128]
        for (int i = tid * 4; i < 64 * DHEAD; i += 1024) {
            int r = i >> 7, c = i & 127;
            *(float4*)&Ks[kswz(r, c)] =
                *(const float4*)(Kg + (long)(j0 + r) * DHEAD + c);
            *(float4*)&Vs[r * 128 + c] =
                *(const float4*)(Vg + (long)(j0 + r) * DHEAD + c);
        }
        __syncthreads();

        // S tile: rows ty*4+i, cols tx*4+jj; dot over DH=128
        float s[4][4];
#pragma unroll
        for (int i = 0; i < 4; i++)
#pragma unroll
            for (int jj = 0; jj < 4; jj++) s[i][jj] = 0.0f;

        for (int d = 0; d < DHEAD; d += 4) {
            float4 qv[4], kv[4];
#pragma unroll
            for (int i = 0; i < 4; i++)
                qv[i] = *(const float4*)&Qs[(ty * 4 + i) * 128 + d];
#pragma unroll
            for (int jj = 0; jj < 4; jj++)
                kv[jj] = *(const float4*)&Ks[kswz(tx * 4 + jj, d)];
#pragma unroll
            for (int i = 0; i < 4; i++)
#pragma unroll
                for (int jj = 0; jj < 4; jj++) {
                    s[i][jj] = fmaf(qv[i].x, kv[jj].x, s[i][jj]);
                    s[i][jj] = fmaf(qv[i].y, kv[jj].y, s[i][jj]);
                    s[i][jj] = fmaf(qv[i].z, kv[jj].z, s[i][jj]);
                    s[i][jj] = fmaf(qv[i].w, kv[jj].w, s[i][jj]);
                }
        }

        // Online softmax. Row stats reduced over the 16 tx lanes (xor 1,2,4,8
        // stays inside the warp: lanes [0..15] ty even, [16..31] ty odd).
#pragma unroll
        for (int i = 0; i < 4; i++) {
            float rm = fmaxf(fmaxf(s[i][0], s[i][1]), fmaxf(s[i][2], s[i][3]));
#pragma unroll
            for (int msk = 1; msk < 16; msk <<= 1)
                rm = fmaxf(rm, __shfl_xor_sync(0xffffffffu, rm, msk));
            const float mn    = fmaxf(m[i], rm);
            const float alpha = __expf(m[i] - mn);
            m[i] = mn;
            float rs = 0.0f;
#pragma unroll
            for (int jj = 0; jj < 4; jj++) {
                float p = __expf(s[i][jj] - mn);
                s[i][jj] = p;
                rs += p;
            }
#pragma unroll
            for (int msk = 1; msk < 16; msk <<= 1)
                rs += __shfl_xor_sync(0xffffffffu, rs, msk);
            l[i] = l[i] * alpha + rs;
#pragma unroll
            for (int j = 0; j < 8; j++) o[i][j] *= alpha;
#pragma unroll
            for (int jj = 0; jj < 4; jj++)
                Ps[(ty * 4 + i) * 68 + tx * 4 + jj] = s[i][jj];
        }
        __syncthreads();

        // O += P @ V : rows ty*4+i, cols tx*8..tx*8+7
#pragma unroll 4
        for (int k2 = 0; k2 < 64; k2++) {
            float p[4];
#pragma unroll
            for (int i = 0; i < 4; i++)
                p[i] = Ps[(ty * 4 + i) * 68 + k2];      // broadcast across tx
            float4 v0 = *(const float4*)&Vs[k2 * 128 + tx * 8];
            float4 v1 = *(const float4*)&Vs[k2 * 128 + tx * 8 + 4];
#pragma unroll
            for (int i = 0; i < 4; i++) {
                o[i][0] = fmaf(p[i], v0.x, o[i][0]);
                o[i][1] = fmaf(p[i], v0.y, o[i][1]);
                o[i][2] = fmaf(p[i], v0.z, o[i][2]);
                o[i][3] = fmaf(p[i], v0.w, o[i][3]);
                o[i][4] = fmaf(p[i], v1.x, o[i][4]);
                o[i][5] = fmaf(p[i], v1.y, o[i][5]);
                o[i][6] = fmaf(p[i], v1.z, o[i][6]);
                o[i][7] = fmaf(p[i], v1.w, o[i][7]);
            }
        }
    }

    // Normalize and write out (merged-head layout)
    float* Og = O + ((long)b * SEQ + q0) * DIM + h * DHEAD;
#pragma unroll
    for (int i = 0; i < 4; i++) {
        const float inv = 1.0f / l[i];
        float4 r0, r1;
        r0.x = o[i][0] * inv; r0.y = o[i][1] * inv;
        r0.z = o[i][2] * inv; r0.w = o[i][3] * inv;
        r1.x = o[i][4] * inv; r1.y = o[i][5] * inv;
        r1.z = o[i][6] * inv; r1.w = o[i][7] * inv;
        *(float4*)(Og + (long)(ty * 4 + i) * DIM + tx * 8)     = r0;
        *(float4*)(Og + (long)(ty * 4 + i) * DIM + tx * 8 + 4) = r1;
    }
}

// ---------------------------------------------------------------------------
extern "C" void kernel_launch(void* const* d_in, const int* in_sizes, int n_in,
                              void* d_out, int out_size)
{
    const float* q  = (const float*)d_in[0];
    const float* k  = (const float*)d_in[1];
    const float* v  = (const float*)d_in[2];
    const float* Wq = (const float*)d_in[3];
    const float* bq = (const float*)d_in[4];
    const float* Wk = (const float*)d_in[5];
    const float* bk = (const float*)d_in[6];
    const float* Wv = (const float*)d_in[7];
    const float* bv = (const float*)d_in[8];
    const float* Wo = (const float*)d_in[9];
    const float* bo = (const float*)d_in[10];
    float* out = (float*)d_out;

    float *qh, *kh, *vh, *ao;
    cudaGetSymbolAddress((void**)&qh, d_qh);
    cudaGetSymbolAddress((void**)&kh, d_kh);
    cudaGetSymbolAddress((void**)&vh, d_vh);
    cudaGetSymbolAddress((void**)&ao, d_ao);

    const int M = BATCH * SEQ;   // 8192

    // Q projection: [8192,2048] = q @ Wq + bq
    gemm_bias<128, 128, 16, 8, 8>
        <<<dim3(DIM / 128, M / 128), 256>>>(q, Wq, bq, qh, M, DIM, DIM);

    // K / V projections: [8192,128]
    gemm_bias<64, 128, 16, 4, 8>
        <<<dim3(DHEAD / 128, M / 64), 256>>>(k, Wk, bk, kh, M, DHEAD, DIM);
    gemm_bias<64, 128, 16, 4, 8>
        <<<dim3(DHEAD / 128, M / 64), 256>>>(v, Wv, bv, vh, M, DHEAD, DIM);

    // Flash attention (dynamic smem 113 KB)
    const int smem_bytes = (3 * 64 * 128 + 64 * 68) * (int)sizeof(float);
    cudaFuncSetAttribute(mqa_flash,
                         cudaFuncAttributeMaxDynamicSharedMemorySize, smem_bytes);
    mqa_flash<<<dim3(SEQ / 64, HEADS, BATCH), 256, smem_bytes>>>(qh, kh, vh, ao);

    // Output projection: out = ao @ Wo + bo
    gemm_bias<128, 128, 16, 8, 8>
        <<<dim3(DIM / 128, M / 128), 256>>>(ao, Wo, bo, out, M, DIM, DIM);
}

// round 6
// speedup vs baseline: 1.4693x; 1.4693x over previous
#include <cuda_runtime.h>
#include <cuda_bf16.h>
#include <cstdint>

#define BATCH 4
#define SEQ   2048
#define DIM   2048
#define HEADS 16
#define DHEAD 128

// Scratch (__device__ globals: allocation-free rule)
__device__ float d_qh[BATCH * SEQ * DIM];     // projected Q fp32
__device__ float d_kh[BATCH * SEQ * DHEAD];   // projected shared K head
__device__ float d_vh[BATCH * SEQ * DHEAD];   // projected shared V head
__device__ float d_ao[BATCH * SEQ * DIM];     // attention out fp32

// ---------------------------------------------------------------------------
// Warp-MMA building blocks (baseline PTX ISA: works on plain sm_103 target)
// ---------------------------------------------------------------------------
__device__ __forceinline__ void mma16816(float* c, const uint32_t* a, const uint32_t* b)
{
    asm volatile(
        "mma.sync.aligned.m16n8k16.row.col.f32.bf16.bf16.f32 "
        "{%0,%1,%2,%3}, {%4,%5,%6,%7}, {%8,%9}, {%0,%1,%2,%3};"
        : "+f"(c[0]), "+f"(c[1]), "+f"(c[2]), "+f"(c[3])
        : "r"(a[0]), "r"(a[1]), "r"(a[2]), "r"(a[3]), "r"(b[0]), "r"(b[1]));
}
#define LDSM4(d, addr) \
    asm volatile("ldmatrix.sync.aligned.m8n8.x4.shared.b16 {%0,%1,%2,%3}, [%4];" \
        : "=r"((d)[0]), "=r"((d)[1]), "=r"((d)[2]), "=r"((d)[3]) : "r"(addr))
#define LDSM4T(d, addr) \
    asm volatile("ldmatrix.sync.aligned.m8n8.x4.trans.shared.b16 {%0,%1,%2,%3}, [%4];" \
        : "=r"((d)[0]), "=r"((d)[1]), "=r"((d)[2]), "=r"((d)[3]) : "r"(addr))

// split 8 fp32 -> 8 bf16 hi + 8 bf16 lo (x = hi + lo, Markidis split)
__device__ __forceinline__ void split8(float4 fa, float4 fb, uint4& hi, uint4& lo)
{
    __nv_bfloat162 h[4], l[4];
    float xs[8] = {fa.x, fa.y, fa.z, fa.w, fb.x, fb.y, fb.z, fb.w};
#pragma unroll
    for (int i = 0; i < 4; i++) {
        float a = xs[2 * i], b = xs[2 * i + 1];
        __nv_bfloat162 hh = __floats2bfloat162_rn(a, b);
        float ra = a - __bfloat162float(hh.x);
        float rb = b - __bfloat162float(hh.y);
        h[i] = hh;
        l[i] = __floats2bfloat162_rn(ra, rb);
    }
    hi = *reinterpret_cast<uint4*>(h);
    lo = *reinterpret_cast<uint4*>(l);
}

// ---------------------------------------------------------------------------
// bf16x3 tensor-core GEMM: C[M,N] = A[M,K](fp32) @ W[K,N](fp32) + bias
// Tile 128x128, BK=32. 256 threads = 8 warps (4 x 2), warp tile 32x64.
// smem element offsets: sAh 0, sAl 4096, sBh 8192, sBl 12288 (bf16 elems).
// A smem: [128 rows][4 chunks of 16B], chunk ^= (row>>1)&3  -> ldmatrix CF.
// B smem: [32 k-rows][16 chunks of 16B], chunk ^= (k&7)     -> ldmatrix.trans CF.
// ---------------------------------------------------------------------------
__global__ void __launch_bounds__(256, 2)
gemm_mma(const float* __restrict__ A, const float* __restrict__ W,
         const float* __restrict__ bias, float* __restrict__ C,
         int M, int N, int K)
{
    __shared__ __nv_bfloat16 smem[4 * 4096];
    const uint32_t sbase = (uint32_t)__cvta_generic_to_shared(smem);
    const int tid = threadIdx.x, lane = tid & 31, wid = tid >> 5;
    const int bm = blockIdx.y * 128, bn = blockIdx.x * 128;
    const int wm = (wid & 3) * 32, wn = (wid >> 2) * 64;

    float c[2][8][4];
#pragma unroll
    for (int i = 0; i < 2; i++)
#pragma unroll
        for (int j = 0; j < 8; j++)
#pragma unroll
            for (int q = 0; q < 4; q++) c[i][j][q] = 0.0f;

    // ldmatrix per-thread row selectors
    const int sub  = lane >> 3;                      // address group 0..3
    const int rsel = (lane & 7) + (sub & 1) * 8;     // A row-in-16 / B k-in-16

    for (int kt = 0; kt < K; kt += 32) {
        __syncthreads();
        {   // A tile: 128 rows x 32 k (fp32 -> hi/lo bf16)
            const int r = tid >> 1, h = tid & 1;
            const float* ag = A + (size_t)(bm + r) * K + kt + h * 16;
            float4 f0 = *(const float4*)ag;
            float4 f1 = *(const float4*)(ag + 4);
            float4 f2 = *(const float4*)(ag + 8);
            float4 f3 = *(const float4*)(ag + 12);
            const int sw = (r >> 1) & 3;
            uint4 hi, lo;
            split8(f0, f1, hi, lo);
            int c0 = (2 * h) ^ sw;
            *(uint4*)(smem + r * 32 + c0 * 8)        = hi;
            *(uint4*)(smem + 4096 + r * 32 + c0 * 8) = lo;
            split8(f2, f3, hi, lo);
            int c1 = (2 * h + 1) ^ sw;
            *(uint4*)(smem + r * 32 + c1 * 8)        = hi;
            *(uint4*)(smem + 4096 + r * 32 + c1 * 8) = lo;
        }
        {   // W tile: 32 k-rows x 128 n (fp32 -> hi/lo bf16), natural [K,N]
            const int kr = tid >> 3, j0 = tid & 7;
            const float* wg = W + (size_t)(kt + kr) * N + bn + j0 * 16;
            float4 f0 = *(const float4*)wg;
            float4 f1 = *(const float4*)(wg + 4);
            float4 f2 = *(const float4*)(wg + 8);
            float4 f3 = *(const float4*)(wg + 12);
            const int sw = kr & 7;
            uint4 hi, lo;
            split8(f0, f1, hi, lo);
            int c0 = (2 * j0) ^ sw;
            *(uint4*)(smem + 8192  + kr * 128 + c0 * 8) = hi;
            *(uint4*)(smem + 12288 + kr * 128 + c0 * 8) = lo;
            split8(f2, f3, hi, lo);
            int c1 = (2 * j0 + 1) ^ sw;
            *(uint4*)(smem + 8192  + kr * 128 + c1 * 8) = hi;
            *(uint4*)(smem + 12288 + kr * 128 + c1 * 8) = lo;
        }
        __syncthreads();

#pragma unroll
        for (int ks = 0; ks < 2; ks++) {
            uint32_t ah[2][4], al[2][4];
#pragma unroll
            for (int mt = 0; mt < 2; mt++) {
                const int row = wm + mt * 16 + rsel;
                const int ch  = (ks * 2 + (sub >> 1)) ^ ((row >> 1) & 3);
                const uint32_t ad = sbase + (uint32_t)(row * 32 + ch * 8) * 2;
                LDSM4(ah[mt], ad);
                LDSM4(al[mt], ad + 8192);
            }
            const int kin = ks * 16 + rsel;      // B k-row for this lane
#pragma unroll
            for (int half = 0; half < 2; half++) {
                uint32_t bh[4][2], bl[4][2];
#pragma unroll
                for (int p = 0; p < 2; p++) {
                    const int nt0 = half * 4 + p * 2 + (sub >> 1);
                    const int ch  = ((wn >> 3) + nt0) ^ (kin & 7);
                    const uint32_t ad =
                        sbase + (uint32_t)(8192 + kin * 128 + ch * 8) * 2;
                    uint32_t t0[4], t1[4];
                    LDSM4T(t0, ad);
                    LDSM4T(t1, ad + 8192);
                    bh[p * 2][0] = t0[0]; bh[p * 2][1] = t0[1];
                    bh[p * 2 + 1][0] = t0[2]; bh[p * 2 + 1][1] = t0[3];
                    bl[p * 2][0] = t1[0]; bl[p * 2][1] = t1[1];
                    bl[p * 2 + 1][0] = t1[2]; bl[p * 2 + 1][1] = t1[3];
                }
#pragma unroll
                for (int mt = 0; mt < 2; mt++)
#pragma unroll
                    for (int ln = 0; ln < 4; ln++) {
                        float* acc = c[mt][half * 4 + ln];
                        mma16816(acc, ah[mt], bh[ln]);   // hi*hi
                        mma16816(acc, ah[mt], bl[ln]);   // hi*lo
                        mma16816(acc, al[mt], bh[ln]);   // lo*hi
                    }
            }
        }
    }

    // Epilogue: fragment -> gmem fp32 + bias
    const int g = lane >> 2, tg = lane & 3;
#pragma unroll
    for (int mt = 0; mt < 2; mt++)
#pragma unroll
        for (int nt = 0; nt < 8; nt++) {
            const int col = bn + wn + nt * 8 + 2 * tg;
            const float2 bb = *(const float2*)(bias + col);
            const int r0 = bm + wm + mt * 16 + g;
            float2 o0, o1;
            o0.x = c[mt][nt][0] + bb.x; o0.y = c[mt][nt][1] + bb.y;
            o1.x = c[mt][nt][2] + bb.x; o1.y = c[mt][nt][3] + bb.y;
            *(float2*)(C + (size_t)r0 * N + col)       = o0;
            *(float2*)(C + (size_t)(r0 + 8) * N + col) = o1;
        }
}

// ---------------------------------------------------------------------------
// Flash attention for MQA (unchanged R3-proven version)
// ---------------------------------------------------------------------------
__device__ __forceinline__ int kswz(int r, int c) {
    int cc = (c >> 2) ^ ((r >> 2) & 7);
    return r * 128 + (cc << 2);
}

__global__ void __launch_bounds__(256)
mqa_flash(const float* __restrict__ Qh, const float* __restrict__ Kh,
          const float* __restrict__ Vh, float* __restrict__ O)
{
    extern __shared__ float smf[];
    float* Qs = smf;
    float* Ks = Qs + 64 * 128;
    float* Vs = Ks + 64 * 128;
    float* Ps = Vs + 64 * 128;

    const int tid = threadIdx.x;
    const int tx  = tid & 15;
    const int ty  = tid >> 4;
    const int b   = blockIdx.z;
    const int h   = blockIdx.y;
    const int q0  = blockIdx.x * 64;
    const float scale = 0.088388347648318447f;

    const float* Qg = Qh + ((long)b * SEQ + q0) * DIM + h * DHEAD;
    for (int i = tid * 4; i < 64 * DHEAD; i += 1024) {
        int r = i >> 7, c = i & 127;
        float4 v = *(const float4*)(Qg + (long)r * DIM + c);
        v.x *= scale; v.y *= scale; v.z *= scale; v.w *= scale;
        *(float4*)&Qs[r * 128 + c] = v;
    }

    float m[4], l[4], o[4][8];
#pragma unroll
    for (int i = 0; i < 4; i++) {
        m[i] = -3.0e38f; l[i] = 0.0f;
#pragma unroll
        for (int j = 0; j < 8; j++) o[i][j] = 0.0f;
    }

    const float* Kg = Kh + (long)b * SEQ * DHEAD;
    const float* Vg = Vh + (long)b * SEQ * DHEAD;

    for (int j0 = 0; j0 < SEQ; j0 += 64) {
        __syncthreads();
        for (int i = tid * 4; i < 64 * DHEAD; i += 1024) {
            int r = i >> 7, c = i & 127;
            *(float4*)&Ks[kswz(r, c)] =
                *(const float4*)(Kg + (long)(j0 + r) * DHEAD + c);
            *(float4*)&Vs[r * 128 + c] =
                *(const float4*)(Vg + (long)(j0 + r) * DHEAD + c);
        }
        __syncthreads();

        float s[4][4];
#pragma unroll
        for (int i = 0; i < 4; i++)
#pragma unroll
            for (int jj = 0; jj < 4; jj++) s[i][jj] = 0.0f;

        for (int d = 0; d < DHEAD; d += 4) {
            float4 qv[4], kv[4];
#pragma unroll
            for (int i = 0; i < 4; i++)
                qv[i] = *(const float4*)&Qs[(ty * 4 + i) * 128 + d];
#pragma unroll
            for (int jj = 0; jj < 4; jj++)
                kv[jj] = *(const float4*)&Ks[kswz(tx * 4 + jj, d)];
#pragma unroll
            for (int i = 0; i < 4; i++)
#pragma unroll
                for (int jj = 0; jj < 4; jj++) {
                    s[i][jj] = fmaf(qv[i].x, kv[jj].x, s[i][jj]);
                    s[i][jj] = fmaf(qv[i].y, kv[jj].y, s[i][jj]);
                    s[i][jj] = fmaf(qv[i].z, kv[jj].z, s[i][jj]);
                    s[i][jj] = fmaf(qv[i].w, kv[jj].w, s[i][jj]);
                }
        }

#pragma unroll
        for (int i = 0; i < 4; i++) {
            float rm = fmaxf(fmaxf(s[i][0], s[i][1]), fmaxf(s[i][2], s[i][3]));
#pragma unroll
            for (int msk = 1; msk < 16; msk <<= 1)
                rm = fmaxf(rm, __shfl_xor_sync(0xffffffffu, rm, msk));
            const float mn    = fmaxf(m[i], rm);
            const float alpha = __expf(m[i] - mn);
            m[i] = mn;
            float rs = 0.0f;
#pragma unroll
            for (int jj = 0; jj < 4; jj++) {
                float p = __expf(s[i][jj] - mn);
                s[i][jj] = p;
                rs += p;
            }
#pragma unroll
            for (int msk = 1; msk < 16; msk <<= 1)
                rs += __shfl_xor_sync(0xffffffffu, rs, msk);
            l[i] = l[i] * alpha + rs;
#pragma unroll
            for (int j = 0; j < 8; j++) o[i][j] *= alpha;
#pragma unroll
            for (int jj = 0; jj < 4; jj++)
                Ps[(ty * 4 + i) * 68 + tx * 4 + jj] = s[i][jj];
        }
        __syncthreads();

#pragma unroll 4
        for (int k2 = 0; k2 < 64; k2++) {
            float p[4];
#pragma unroll
            for (int i = 0; i < 4; i++)
                p[i] = Ps[(ty * 4 + i) * 68 + k2];
            float4 v0 = *(const float4*)&Vs[k2 * 128 + tx * 8];
            float4 v1 = *(const float4*)&Vs[k2 * 128 + tx * 8 + 4];
#pragma unroll
            for (int i = 0; i < 4; i++) {
                o[i][0] = fmaf(p[i], v0.x, o[i][0]);
                o[i][1] = fmaf(p[i], v0.y, o[i][1]);
                o[i][2] = fmaf(p[i], v0.z, o[i][2]);
                o[i][3] = fmaf(p[i], v0.w, o[i][3]);
                o[i][4] = fmaf(p[i], v1.x, o[i][4]);
                o[i][5] = fmaf(p[i], v1.y, o[i][5]);
                o[i][6] = fmaf(p[i], v1.z, o[i][6]);
                o[i][7] = fmaf(p[i], v1.w, o[i][7]);
            }
        }
    }

    float* Og = O + ((long)b * SEQ + q0) * DIM + h * DHEAD;
#pragma unroll
    for (int i = 0; i < 4; i++) {
        const float inv = 1.0f / l[i];
        float4 r0, r1;
        r0.x = o[i][0] * inv; r0.y = o[i][1] * inv;
        r0.z = o[i][2] * inv; r0.w = o[i][3] * inv;
        r1.x = o[i][4] * inv; r1.y = o[i][5] * inv;
        r1.z = o[i][6] * inv; r1.w = o[i][7] * inv;
        *(float4*)(Og + (long)(ty * 4 + i) * DIM + tx * 8)     = r0;
        *(float4*)(Og + (long)(ty * 4 + i) * DIM + tx * 8 + 4) = r1;
    }
}

// ---------------------------------------------------------------------------
extern "C" void kernel_launch(void* const* d_in, const int* in_sizes, int n_in,
                              void* d_out, int out_size)
{
    const float* q  = (const float*)d_in[0];
    const float* k  = (const float*)d_in[1];
    const float* v  = (const float*)d_in[2];
    const float* Wq = (const float*)d_in[3];
    const float* bq = (const float*)d_in[4];
    const float* Wk = (const float*)d_in[5];
    const float* bk = (const float*)d_in[6];
    const float* Wv = (const float*)d_in[7];
    const float* bv = (const float*)d_in[8];
    const float* Wo = (const float*)d_in[9];
    const float* bo = (const float*)d_in[10];
    float* out = (float*)d_out;

    float *qh, *kh, *vh, *ao;
    cudaGetSymbolAddress((void**)&qh, d_qh);
    cudaGetSymbolAddress((void**)&kh, d_kh);
    cudaGetSymbolAddress((void**)&vh, d_vh);
    cudaGetSymbolAddress((void**)&ao, d_ao);

    const int M = BATCH * SEQ;   // 8192

    const int smem_attn = (3 * 64 * 128 + 64 * 68) * (int)sizeof(float);
    cudaFuncSetAttribute(mqa_flash, cudaFuncAttributeMaxDynamicSharedMemorySize,
                         smem_attn);

    // Q projection: [8192, 2048]
    gemm_mma<<<dim3(DIM / 128, M / 128), 256>>>(q, Wq, bq, qh, M, DIM, DIM);
    // K / V projections: [8192, 128]
    gemm_mma<<<dim3(DHEAD / 128, M / 128), 256>>>(k, Wk, bk, kh, M, DHEAD, DIM);
    gemm_mma<<<dim3(DHEAD / 128, M / 128), 256>>>(v, Wv, bv, vh, M, DHEAD, DIM);

    // Attention (SIMT flash)
    mqa_flash<<<dim3(SEQ / 64, HEADS, BATCH), 256, smem_attn>>>(qh, kh, vh, ao);

    // Output projection
    gemm_mma<<<dim3(DIM / 128, M / 128), 256>>>(ao, Wo, bo, out, M, DIM, DIM);
}

// round 7
// speedup vs baseline: 2.9864x; 2.0324x over previous
#include <cuda_runtime.h>
#include <cuda_bf16.h>
#include <cstdint>

#define BATCH 4
#define SEQ   2048
#define DIM   2048
#define HEADS 16
#define DHEAD 128

// Scratch (__device__ globals: allocation-free rule)
__device__ float d_qh[BATCH * SEQ * DIM];     // projected Q fp32
__device__ float d_kh[BATCH * SEQ * DHEAD];   // projected shared K head
__device__ float d_vh[BATCH * SEQ * DHEAD];   // projected shared V head
__device__ float d_ao[BATCH * SEQ * DIM];     // attention out fp32
// bf16 hi/lo splits for tensorized attention
__device__ __nv_bfloat16 d_qhi[BATCH * SEQ * DIM],   d_qlo[BATCH * SEQ * DIM];
__device__ __nv_bfloat16 d_khi[BATCH * SEQ * DHEAD], d_klo[BATCH * SEQ * DHEAD];
__device__ __nv_bfloat16 d_vhi[BATCH * SEQ * DHEAD], d_vlo[BATCH * SEQ * DHEAD];

// ---------------------------------------------------------------------------
// Warp-MMA building blocks (baseline PTX ISA, plain sm_103 target)
// ---------------------------------------------------------------------------
__device__ __forceinline__ void mma16816(float* c, const uint32_t* a, const uint32_t* b)
{
    asm volatile(
        "mma.sync.aligned.m16n8k16.row.col.f32.bf16.bf16.f32 "
        "{%0,%1,%2,%3}, {%4,%5,%6,%7}, {%8,%9}, {%0,%1,%2,%3};"
        : "+f"(c[0]), "+f"(c[1]), "+f"(c[2]), "+f"(c[3])
        : "r"(a[0]), "r"(a[1]), "r"(a[2]), "r"(a[3]), "r"(b[0]), "r"(b[1]));
}
#define LDSM4(d, addr) \
    asm volatile("ldmatrix.sync.aligned.m8n8.x4.shared.b16 {%0,%1,%2,%3}, [%4];" \
        : "=r"((d)[0]), "=r"((d)[1]), "=r"((d)[2]), "=r"((d)[3]) : "r"(addr))
#define LDSM4T(d, addr) \
    asm volatile("ldmatrix.sync.aligned.m8n8.x4.trans.shared.b16 {%0,%1,%2,%3}, [%4];" \
        : "=r"((d)[0]), "=r"((d)[1]), "=r"((d)[2]), "=r"((d)[3]) : "r"(addr))

// fast exp2 on FMA/ALU pipes (x <= 0). |rel err| ~2.4e-6.
__device__ __forceinline__ float exp2_fast(float x)
{
    x = fmaxf(x, -100.0f);
    float z  = x + 12582912.0f;            // round-to-nearest int (2^23*1.5)
    int   e  = __float_as_int(z);          // low mantissa bits = int(x)+bias
    float f  = x - (z - 12582912.0f);      // frac in [-0.5, 0.5]
    float p  = 1.3333558146e-3f;
    p = fmaf(p, f, 9.6181291078e-3f);
    p = fmaf(p, f, 5.5504108664e-2f);
    p = fmaf(p, f, 2.4022650696e-1f);
    p = fmaf(p, f, 6.9314718056e-1f);
    p = fmaf(p, f, 1.0f);
    return __int_as_float(__float_as_int(p) + (e << 23));
}

// split 8 fp32 -> 8 bf16 hi + 8 bf16 lo (x = hi + lo)
__device__ __forceinline__ void split8(float4 fa, float4 fb, uint4& hi, uint4& lo)
{
    __nv_bfloat162 h[4], l[4];
    float xs[8] = {fa.x, fa.y, fa.z, fa.w, fb.x, fb.y, fb.z, fb.w};
#pragma unroll
    for (int i = 0; i < 4; i++) {
        float a = xs[2 * i], b = xs[2 * i + 1];
        __nv_bfloat162 hh = __floats2bfloat162_rn(a, b);
        float ra = a - __bfloat162float(hh.x);
        float rb = b - __bfloat162float(hh.y);
        h[i] = hh;
        l[i] = __floats2bfloat162_rn(ra, rb);
    }
    hi = *reinterpret_cast<uint4*>(h);
    lo = *reinterpret_cast<uint4*>(l);
}

// ---------------------------------------------------------------------------
// bf16x3 tensor-core GEMM (R6-proven): C[M,N] = A[M,K] @ W[K,N] + bias
// ---------------------------------------------------------------------------
__global__ void __launch_bounds__(256, 2)
gemm_mma(const float* __restrict__ A, const float* __restrict__ W,
         const float* __restrict__ bias, float* __restrict__ C,
         int M, int N, int K)
{
    __shared__ __nv_bfloat16 smem[4 * 4096];
    const uint32_t sbase = (uint32_t)__cvta_generic_to_shared(smem);
    const int tid = threadIdx.x, lane = tid & 31, wid = tid >> 5;
    const int bm = blockIdx.y * 128, bn = blockIdx.x * 128;
    const int wm = (wid & 3) * 32, wn = (wid >> 2) * 64;

    float c[2][8][4];
#pragma unroll
    for (int i = 0; i < 2; i++)
#pragma unroll
        for (int j = 0; j < 8; j++)
#pragma unroll
            for (int q = 0; q < 4; q++) c[i][j][q] = 0.0f;

    const int sub  = lane >> 3;
    const int rsel = (lane & 7) + (sub & 1) * 8;

    for (int kt = 0; kt < K; kt += 32) {
        __syncthreads();
        {   // A tile
            const int r = tid >> 1, h = tid & 1;
            const float* ag = A + (size_t)(bm + r) * K + kt + h * 16;
            float4 f0 = *(const float4*)ag;
            float4 f1 = *(const float4*)(ag + 4);
            float4 f2 = *(const float4*)(ag + 8);
            float4 f3 = *(const float4*)(ag + 12);
            const int sw = (r >> 1) & 3;
            uint4 hi, lo;
            split8(f0, f1, hi, lo);
            int c0 = (2 * h) ^ sw;
            *(uint4*)(smem + r * 32 + c0 * 8)        = hi;
            *(uint4*)(smem + 4096 + r * 32 + c0 * 8) = lo;
            split8(f2, f3, hi, lo);
            int c1 = (2 * h + 1) ^ sw;
            *(uint4*)(smem + r * 32 + c1 * 8)        = hi;
            *(uint4*)(smem + 4096 + r * 32 + c1 * 8) = lo;
        }
        {   // W tile
            const int kr = tid >> 3, j0 = tid & 7;
            const float* wg = W + (size_t)(kt + kr) * N + bn + j0 * 16;
            float4 f0 = *(const float4*)wg;
            float4 f1 = *(const float4*)(wg + 4);
            float4 f2 = *(const float4*)(wg + 8);
            float4 f3 = *(const float4*)(wg + 12);
            const int sw = kr & 7;
            uint4 hi, lo;
            split8(f0, f1, hi, lo);
            int c0 = (2 * j0) ^ sw;
            *(uint4*)(smem + 8192  + kr * 128 + c0 * 8) = hi;
            *(uint4*)(smem + 12288 + kr * 128 + c0 * 8) = lo;
            split8(f2, f3, hi, lo);
            int c1 = (2 * j0 + 1) ^ sw;
            *(uint4*)(smem + 8192  + kr * 128 + c1 * 8) = hi;
            *(uint4*)(smem + 12288 + kr * 128 + c1 * 8) = lo;
        }
        __syncthreads();

#pragma unroll
        for (int ks = 0; ks < 2; ks++) {
            uint32_t ah[2][4], al[2][4];
#pragma unroll
            for (int mt = 0; mt < 2; mt++) {
                const int row = wm + mt * 16 + rsel;
                const int ch  = (ks * 2 + (sub >> 1)) ^ ((row >> 1) & 3);
                const uint32_t ad = sbase + (uint32_t)(row * 32 + ch * 8) * 2;
                LDSM4(ah[mt], ad);
                LDSM4(al[mt], ad + 8192);
            }
            const int kin = ks * 16 + rsel;
#pragma unroll
            for (int half = 0; half < 2; half++) {
                uint32_t bh[4][2], bl[4][2];
#pragma unroll
                for (int p = 0; p < 2; p++) {
                    const int nt0 = half * 4 + p * 2 + (sub >> 1);
                    const int ch  = ((wn >> 3) + nt0) ^ (kin & 7);
                    const uint32_t ad =
                        sbase + (uint32_t)(8192 + kin * 128 + ch * 8) * 2;
                    uint32_t t0[4], t1[4];
                    LDSM4T(t0, ad);
                    LDSM4T(t1, ad + 8192);
                    bh[p * 2][0] = t0[0]; bh[p * 2][1] = t0[1];
                    bh[p * 2 + 1][0] = t0[2]; bh[p * 2 + 1][1] = t0[3];
                    bl[p * 2][0] = t1[0]; bl[p * 2][1] = t1[1];
                    bl[p * 2 + 1][0] = t1[2]; bl[p * 2 + 1][1] = t1[3];
                }
#pragma unroll
                for (int mt = 0; mt < 2; mt++)
#pragma unroll
                    for (int ln = 0; ln < 4; ln++) {
                        float* acc = c[mt][half * 4 + ln];
                        mma16816(acc, ah[mt], bh[ln]);
                        mma16816(acc, ah[mt], bl[ln]);
                        mma16816(acc, al[mt], bh[ln]);
                    }
            }
        }
    }

    const int g = lane >> 2, tg = lane & 3;
#pragma unroll
    for (int mt = 0; mt < 2; mt++)
#pragma unroll
        for (int nt = 0; nt < 8; nt++) {
            const int col = bn + wn + nt * 8 + 2 * tg;
            const float2 bb = *(const float2*)(bias + col);
            const int r0 = bm + wm + mt * 16 + g;
            float2 o0, o1;
            o0.x = c[mt][nt][0] + bb.x; o0.y = c[mt][nt][1] + bb.y;
            o1.x = c[mt][nt][2] + bb.x; o1.y = c[mt][nt][3] + bb.y;
            *(float2*)(C + (size_t)r0 * N + col)       = o0;
            *(float2*)(C + (size_t)(r0 + 8) * N + col) = o1;
        }
}

// ---------------------------------------------------------------------------
// split fp32 -> bf16 hi/lo with optional scale folded in
// ---------------------------------------------------------------------------
__global__ void __launch_bounds__(256)
split_scale(const float4* __restrict__ x, uint2* __restrict__ hi,
            uint2* __restrict__ lo, float s, int n4)
{
    int i = blockIdx.x * 256 + threadIdx.x;
    if (i >= n4) return;
    float4 v = x[i];
    v.x *= s; v.y *= s; v.z *= s; v.w *= s;
    __nv_bfloat162 h01 = __floats2bfloat162_rn(v.x, v.y);
    __nv_bfloat162 h23 = __floats2bfloat162_rn(v.z, v.w);
    __nv_bfloat162 l01 = __floats2bfloat162_rn(v.x - __bfloat162float(h01.x),
                                               v.y - __bfloat162float(h01.y));
    __nv_bfloat162 l23 = __floats2bfloat162_rn(v.z - __bfloat162float(h23.x),
                                               v.w - __bfloat162float(h23.y));
    uint2 ho, lo2;
    ho.x  = *(uint32_t*)&h01; ho.y  = *(uint32_t*)&h23;
    lo2.x = *(uint32_t*)&l01; lo2.y = *(uint32_t*)&l23;
    hi[i] = ho;
    lo[i] = lo2;
}

// ---------------------------------------------------------------------------
// Tensorized flash attention (MQA, bf16x3, FMA-pipe exp2)
// CTA: 64 q-rows x 1 head; 4 warps (16 rows each); KV tiles of 64.
// smem bytes: Qhi 0, Qlo 16384, Khi 32768, Klo 49152, Vhi 65536, Vlo 81920.
// Row layout everywhere: [row][16 chunks of 16B], chunk ^= (row & 7).
// ---------------------------------------------------------------------------
__global__ void __launch_bounds__(128, 2)
mqa_flash_tc(const __nv_bfloat16* __restrict__ Qhi, const __nv_bfloat16* __restrict__ Qlo,
             const __nv_bfloat16* __restrict__ Khi, const __nv_bfloat16* __restrict__ Klo,
             const __nv_bfloat16* __restrict__ Vhi, const __nv_bfloat16* __restrict__ Vlo,
             float* __restrict__ O)
{
    extern __shared__ __align__(16) __nv_bfloat16 sm[];
    const uint32_t sb = (uint32_t)__cvta_generic_to_shared(sm);
    const int tid = threadIdx.x, lane = tid & 31, wid = tid >> 5;
    const int b = blockIdx.z, h = blockIdx.y, q0 = blockIdx.x * 64;
    const int wm = wid * 16;

    // ---- Q tile 64x128 hi/lo, swizzled ----
    {
        const size_t qbase = ((size_t)b * SEQ + q0) * DIM + h * DHEAD;
#pragma unroll
        for (int i = tid; i < 1024; i += 128) {
            int r = i >> 4, c = i & 15;
            int pc = c ^ (r & 7);
            const size_t g = qbase + (size_t)r * DIM + c * 8;
            *(uint4*)(sm + r * 128 + pc * 8)        = *(const uint4*)(Qhi + g);
            *(uint4*)(sm + 8192 + r * 128 + pc * 8) = *(const uint4*)(Qlo + g);
        }
    }
    __syncthreads();

    // ---- Q fragments (held in registers for the whole kernel) ----
    uint32_t qfh[8][4], qfl[8][4];
    {
        const int r = wm + (lane & 7) + ((lane >> 3) & 1) * 8;
#pragma unroll
        for (int d = 0; d < 8; d++) {
            int cc = 2 * d + (lane >> 4);
            uint32_t ad = sb + (uint32_t)(r * 128 + ((cc ^ (r & 7)) * 8)) * 2;
            LDSM4(qfh[d], ad);
            LDSM4(qfl[d], ad + 16384);
        }
    }

    float m0 = -1e30f, m1 = -1e30f, l0 = 0.f, l1 = 0.f;
    float o[16][4];
#pragma unroll
    for (int nt = 0; nt < 16; nt++)
#pragma unroll
        for (int q = 0; q < 4; q++) o[nt][q] = 0.f;

    const size_t kvbase = (size_t)b * SEQ * DHEAD;

    for (int j0 = 0; j0 < SEQ; j0 += 64) {
        __syncthreads();
#pragma unroll
        for (int i = tid; i < 1024; i += 128) {
            int r = i >> 4, c = i & 15;
            int pc = c ^ (r & 7);
            const size_t g = kvbase + (size_t)(j0 + r) * DHEAD + c * 8;
            int so = r * 128 + pc * 8;
            *(uint4*)(sm + 16384 + so) = *(const uint4*)(Khi + g);
            *(uint4*)(sm + 24576 + so) = *(const uint4*)(Klo + g);
            *(uint4*)(sm + 32768 + so) = *(const uint4*)(Vhi + g);
            *(uint4*)(sm + 40960 + so) = *(const uint4*)(Vlo + g);
        }
        __syncthreads();

        // ---- S = Q K^T (bf16x3). Warp tile 16x64 = 8 n-tiles. ----
        float s[8][4];
#pragma unroll
        for (int j = 0; j < 8; j++)
#pragma unroll
            for (int q = 0; q < 4; q++) s[j][q] = 0.f;
        {
            const int rr = (lane & 7) + ((lane >> 3) & 1) * 8;
#pragma unroll
            for (int d = 0; d < 8; d++) {
                int cc = 2 * d + (lane >> 4);
#pragma unroll
                for (int jb = 0; jb < 4; jb++) {
                    int r = jb * 16 + rr;
                    uint32_t ad = sb + 32768u +
                        (uint32_t)(r * 128 + ((cc ^ (r & 7)) * 8)) * 2;
                    uint32_t kh[4], kl[4];
                    LDSM4(kh, ad);             // Khi
                    LDSM4(kl, ad + 16384);     // Klo
                    uint32_t b0h[2] = {kh[0], kh[2]}, b1h[2] = {kh[1], kh[3]};
                    uint32_t b0l[2] = {kl[0], kl[2]}, b1l[2] = {kl[1], kl[3]};
                    mma16816(s[2 * jb],     qfh[d], b0h);
                    mma16816(s[2 * jb],     qfh[d], b0l);
                    mma16816(s[2 * jb],     qfl[d], b0h);
                    mma16816(s[2 * jb + 1], qfh[d], b1h);
                    mma16816(s[2 * jb + 1], qfh[d], b1l);
                    mma16816(s[2 * jb + 1], qfl[d], b1h);
                }
            }
        }

        // ---- online softmax (log2 domain; scale*log2e folded into Q) ----
        float rm0 = s[0][0], rm1 = s[0][2];
#pragma unroll
        for (int j = 0; j < 8; j++) {
            rm0 = fmaxf(rm0, fmaxf(s[j][0], s[j][1]));
            rm1 = fmaxf(rm1, fmaxf(s[j][2], s[j][3]));
        }
        rm0 = fmaxf(rm0, __shfl_xor_sync(0xffffffffu, rm0, 1));
        rm0 = fmaxf(rm0, __shfl_xor_sync(0xffffffffu, rm0, 2));
        rm1 = fmaxf(rm1, __shfl_xor_sync(0xffffffffu, rm1, 1));
        rm1 = fmaxf(rm1, __shfl_xor_sync(0xffffffffu, rm1, 2));
        const float mn0 = fmaxf(m0, rm0), mn1 = fmaxf(m1, rm1);
        const float a0 = exp2_fast(m0 - mn0), a1 = exp2_fast(m1 - mn1);
        m0 = mn0; m1 = mn1;
        float rs0 = 0.f, rs1 = 0.f;
#pragma unroll
        for (int j = 0; j < 8; j++) {
            float p0 = exp2_fast(s[j][0] - mn0); s[j][0] = p0;
            float p1 = exp2_fast(s[j][1] - mn0); s[j][1] = p1;
            float p2 = exp2_fast(s[j][2] - mn1); s[j][2] = p2;
            float p3 = exp2_fast(s[j][3] - mn1); s[j][3] = p3;
            rs0 += p0 + p1; rs1 += p2 + p3;
        }
        rs0 += __shfl_xor_sync(0xffffffffu, rs0, 1);
        rs0 += __shfl_xor_sync(0xffffffffu, rs0, 2);
        rs1 += __shfl_xor_sync(0xffffffffu, rs1, 1);
        rs1 += __shfl_xor_sync(0xffffffffu, rs1, 2);
        l0 = l0 * a0 + rs0;
        l1 = l1 * a1 + rs1;
#pragma unroll
        for (int nt = 0; nt < 16; nt++) {
            o[nt][0] *= a0; o[nt][1] *= a0; o[nt][2] *= a1; o[nt][3] *= a1;
        }

        // ---- P fragments (C-frag -> A-frag register remap, hi/lo split) ----
        uint32_t ph[4][4], pl[4][4];
#pragma unroll
        for (int jp = 0; jp < 4; jp++)
#pragma unroll
            for (int idx = 0; idx < 4; idx++) {
                float x0 = s[2 * jp + (idx >> 1)][(idx & 1) * 2 + 0];
                float x1 = s[2 * jp + (idx >> 1)][(idx & 1) * 2 + 1];
                __nv_bfloat162 hh = __floats2bfloat162_rn(x0, x1);
                __nv_bfloat162 ll = __floats2bfloat162_rn(
                    x0 - __bfloat162float(hh.x), x1 - __bfloat162float(hh.y));
                ph[jp][idx] = *(uint32_t*)&hh;
                pl[jp][idx] = *(uint32_t*)&ll;
            }

        // ---- O += P V (bf16x3) ----
        {
            const int rv = (lane & 7) + ((lane >> 3) & 1) * 8;
#pragma unroll
            for (int g2 = 0; g2 < 8; g2++) {
                int cc = 2 * g2 + (lane >> 4);
#pragma unroll
                for (int jp = 0; jp < 4; jp++) {
                    int r = jp * 16 + rv;
                    uint32_t ad = sb + 65536u +
                        (uint32_t)(r * 128 + ((cc ^ (r & 7)) * 8)) * 2;
                    uint32_t vh[4], vl[4];
                    LDSM4T(vh, ad);            // Vhi
                    LDSM4T(vl, ad + 16384);    // Vlo
                    uint32_t b0h[2] = {vh[0], vh[1]}, b1h[2] = {vh[2], vh[3]};
                    uint32_t b0l[2] = {vl[0], vl[1]}, b1l[2] = {vl[2], vl[3]};
                    mma16816(o[2 * g2],     ph[jp], b0h);
                    mma16816(o[2 * g2],     ph[jp], b0l);
                    mma16816(o[2 * g2],     pl[jp], b0h);
                    mma16816(o[2 * g2 + 1], ph[jp], b1h);
                    mma16816(o[2 * g2 + 1], ph[jp], b1l);
                    mma16816(o[2 * g2 + 1], pl[jp], b1h);
                }
            }
        }
    }

    // ---- epilogue: normalize, write fp32 merged-head layout ----
    const float i0 = 1.0f / l0, i1 = 1.0f / l1;
    const int g = lane >> 2, t = lane & 3;
    const size_t ob = ((size_t)b * SEQ + q0 + wm) * DIM + h * DHEAD;
#pragma unroll
    for (int nt = 0; nt < 16; nt++) {
        int col = nt * 8 + 2 * t;
        float2 v0, v1;
        v0.x = o[nt][0] * i0; v0.y = o[nt][1] * i0;
        v1.x = o[nt][2] * i1; v1.y = o[nt][3] * i1;
        *(float2*)(O + ob + (size_t)g * DIM + col)       = v0;
        *(float2*)(O + ob + (size_t)(g + 8) * DIM + col) = v1;
    }
}

// ---------------------------------------------------------------------------
extern "C" void kernel_launch(void* const* d_in, const int* in_sizes, int n_in,
                              void* d_out, int out_size)
{
    const float* q  = (const float*)d_in[0];
    const float* k  = (const float*)d_in[1];
    const float* v  = (const float*)d_in[2];
    const float* Wq = (const float*)d_in[3];
    const float* bq = (const float*)d_in[4];
    const float* Wk = (const float*)d_in[5];
    const float* bk = (const float*)d_in[6];
    const float* Wv = (const float*)d_in[7];
    const float* bv = (const float*)d_in[8];
    const float* Wo = (const float*)d_in[9];
    const float* bo = (const float*)d_in[10];
    float* out = (float*)d_out;

    float *qh, *kh, *vh, *ao;
    cudaGetSymbolAddress((void**)&qh, d_qh);
    cudaGetSymbolAddress((void**)&kh, d_kh);
    cudaGetSymbolAddress((void**)&vh, d_vh);
    cudaGetSymbolAddress((void**)&ao, d_ao);
    __nv_bfloat16 *qhi, *qlo, *khi, *klo, *vhi, *vlo;
    cudaGetSymbolAddress((void**)&qhi, d_qhi);
    cudaGetSymbolAddress((void**)&qlo, d_qlo);
    cudaGetSymbolAddress((void**)&khi, d_khi);
    cudaGetSymbolAddress((void**)&klo, d_klo);
    cudaGetSymbolAddress((void**)&vhi, d_vhi);
    cudaGetSymbolAddress((void**)&vlo, d_vlo);

    const int M = BATCH * SEQ;   // 8192
    // scale(1/sqrt(128)) * log2(e) folded into Q
    const float SCL = 0.1275174414f;

    const int smem_attn = 96 * 1024;
    cudaFuncSetAttribute(mqa_flash_tc,
                         cudaFuncAttributeMaxDynamicSharedMemorySize, smem_attn);

    // Projections (tensor cores, bf16x3)
    gemm_mma<<<dim3(DIM / 128, M / 128), 256>>>(q, Wq, bq, qh, M, DIM, DIM);
    gemm_mma<<<dim3(DHEAD / 128, M / 128), 256>>>(k, Wk, bk, kh, M, DHEAD, DIM);
    gemm_mma<<<dim3(DHEAD / 128, M / 128), 256>>>(v, Wv, bv, vh, M, DHEAD, DIM);

    // hi/lo splits for attention operands
    const int nq4 = M * DIM / 4;
    const int nk4 = M * DHEAD / 4;
    split_scale<<<(nq4 + 255) / 256, 256>>>((const float4*)qh, (uint2*)qhi,
                                            (uint2*)qlo, SCL, nq4);
    split_scale<<<(nk4 + 255) / 256, 256>>>((const float4*)kh, (uint2*)khi,
                                            (uint2*)klo, 1.0f, nk4);
    split_scale<<<(nk4 + 255) / 256, 256>>>((const float4*)vh, (uint2*)vhi,
                                            (uint2*)vlo, 1.0f, nk4);

    // Tensorized flash attention
    mqa_flash_tc<<<dim3(SEQ / 64, HEADS, BATCH), 128, smem_attn>>>(
        qhi, qlo, khi, klo, vhi, vlo, ao);

    // Output projection
    gemm_mma<<<dim3(DIM / 128, M / 128), 256>>>(ao, Wo, bo, out, M, DIM, DIM);
}

// round 8
// speedup vs baseline: 3.9610x; 1.3264x over previous
#include <cuda_runtime.h>
#include <cuda_bf16.h>
#include <cstdint>

#define BATCH 4
#define SEQ   2048
#define DIM   2048
#define HEADS 16
#define DHEAD 128

// ---------------------------------------------------------------------------
// Scratch (__device__ globals: allocation-free rule). All bf16 hi/lo pairs.
// ---------------------------------------------------------------------------
__device__ __nv_bfloat16 d_iq_h[BATCH * SEQ * DIM], d_iq_l[BATCH * SEQ * DIM];
__device__ __nv_bfloat16 d_ik_h[BATCH * SEQ * DIM], d_ik_l[BATCH * SEQ * DIM];
__device__ __nv_bfloat16 d_iv_h[BATCH * SEQ * DIM], d_iv_l[BATCH * SEQ * DIM];
__device__ __nv_bfloat16 d_wq_h[DIM * DIM],   d_wq_l[DIM * DIM];
__device__ __nv_bfloat16 d_wo_h[DIM * DIM],   d_wo_l[DIM * DIM];
__device__ __nv_bfloat16 d_wk_h[DIM * DHEAD], d_wk_l[DIM * DHEAD];
__device__ __nv_bfloat16 d_wv_h[DIM * DHEAD], d_wv_l[DIM * DHEAD];
__device__ __nv_bfloat16 d_q_h[BATCH * SEQ * DIM],   d_q_l[BATCH * SEQ * DIM];
__device__ __nv_bfloat16 d_k_h[BATCH * SEQ * DHEAD], d_k_l[BATCH * SEQ * DHEAD];
__device__ __nv_bfloat16 d_v_h[BATCH * SEQ * DHEAD], d_v_l[BATCH * SEQ * DHEAD];
__device__ __nv_bfloat16 d_ao_h[BATCH * SEQ * DIM],  d_ao_l[BATCH * SEQ * DIM];

// ---------------------------------------------------------------------------
// PTX building blocks (baseline ISA, plain sm_103 target)
// ---------------------------------------------------------------------------
__device__ __forceinline__ void mma16816(float* c, const uint32_t* a, const uint32_t* b)
{
    asm volatile(
        "mma.sync.aligned.m16n8k16.row.col.f32.bf16.bf16.f32 "
        "{%0,%1,%2,%3}, {%4,%5,%6,%7}, {%8,%9}, {%0,%1,%2,%3};"
        : "+f"(c[0]), "+f"(c[1]), "+f"(c[2]), "+f"(c[3])
        : "r"(a[0]), "r"(a[1]), "r"(a[2]), "r"(a[3]), "r"(b[0]), "r"(b[1]));
}
#define LDSM4(d, addr) \
    asm volatile("ldmatrix.sync.aligned.m8n8.x4.shared.b16 {%0,%1,%2,%3}, [%4];" \
        : "=r"((d)[0]), "=r"((d)[1]), "=r"((d)[2]), "=r"((d)[3]) : "r"(addr))
#define LDSM4T(d, addr) \
    asm volatile("ldmatrix.sync.aligned.m8n8.x4.trans.shared.b16 {%0,%1,%2,%3}, [%4];" \
        : "=r"((d)[0]), "=r"((d)[1]), "=r"((d)[2]), "=r"((d)[3]) : "r"(addr))
__device__ __forceinline__ void cpa16(uint32_t dst, const void* src)
{
    asm volatile("cp.async.cg.shared.global [%0], [%1], 16;" :: "r"(dst), "l"(src));
}
#define CP_COMMIT() asm volatile("cp.async.commit_group;")
#define CP_WAIT1()  asm volatile("cp.async.wait_group 1;")

// fast exp2 on FMA/ALU pipes. |rel err| ~2.4e-6.
__device__ __forceinline__ float exp2_fast(float x)
{
    x = fmaxf(x, -100.0f);
    float z  = x + 12582912.0f;
    int   e  = __float_as_int(z);
    float f  = x - (z - 12582912.0f);
    float p  = 1.3333558146e-3f;
    p = fmaf(p, f, 9.6181291078e-3f);
    p = fmaf(p, f, 5.5504108664e-2f);
    p = fmaf(p, f, 2.4022650696e-1f);
    p = fmaf(p, f, 6.9314718056e-1f);
    p = fmaf(p, f, 1.0f);
    return __int_as_float(__float_as_int(p) + (e << 23));
}

// ---------------------------------------------------------------------------
// fp32 -> bf16 hi/lo split (optionally scaled)
// ---------------------------------------------------------------------------
__global__ void __launch_bounds__(256)
split_scale(const float4* __restrict__ x, uint2* __restrict__ hi,
            uint2* __restrict__ lo, float s, int n4)
{
    int i = blockIdx.x * 256 + threadIdx.x;
    if (i >= n4) return;
    float4 v = x[i];
    v.x *= s; v.y *= s; v.z *= s; v.w *= s;
    __nv_bfloat162 h01 = __floats2bfloat162_rn(v.x, v.y);
    __nv_bfloat162 h23 = __floats2bfloat162_rn(v.z, v.w);
    __nv_bfloat162 l01 = __floats2bfloat162_rn(v.x - __bfloat162float(h01.x),
                                               v.y - __bfloat162float(h01.y));
    __nv_bfloat162 l23 = __floats2bfloat162_rn(v.z - __bfloat162float(h23.x),
                                               v.w - __bfloat162float(h23.y));
    uint2 ho, lo2;
    ho.x  = *(uint32_t*)&h01; ho.y  = *(uint32_t*)&h23;
    lo2.x = *(uint32_t*)&l01; lo2.y = *(uint32_t*)&l23;
    hi[i] = ho;
    lo[i] = lo2;
}

// ---------------------------------------------------------------------------
// Pipelined bf16x3 GEMM: C = A(hi+lo) @ W(hi+lo) + bias*bscale
// A [M,K] bf16 split, W [K,N] bf16 split. Tile 128x128, BK=32, 3-stage cp.async.
// Stage layout (elements): Ahi 0, Alo 4096, Whi 8192, Wlo 12288; stride 16384.
// grid.z selects op (for fused K/V projection launch).
// ---------------------------------------------------------------------------
struct GemmOp {
    const __nv_bfloat16 *Ahi, *Alo, *Whi, *Wlo;
    const float* bias;
    float bscale;
    float* Cf;
    __nv_bfloat16 *Chi, *Clo;
};
struct GemmArgs { GemmOp op[2]; };

template <bool SPLIT>
__global__ void __launch_bounds__(256, 2)
gemm_bf16x3(GemmArgs ga, int M, int N, int K)
{
    extern __shared__ __align__(16) __nv_bfloat16 gsm[];
    const GemmOp g = ga.op[blockIdx.z];
    const uint32_t sbase = (uint32_t)__cvta_generic_to_shared(gsm);
    const int tid = threadIdx.x, lane = tid & 31, wid = tid >> 5;
    const int bm = blockIdx.y * 128, bn = blockIdx.x * 128;
    const int wm = (wid & 3) * 32, wn = (wid >> 2) * 64;
    const int niter = K >> 5;

    float c[2][8][4];
#pragma unroll
    for (int i = 0; i < 2; i++)
#pragma unroll
        for (int j = 0; j < 8; j++)
#pragma unroll
            for (int q = 0; q < 4; q++) c[i][j][q] = 0.0f;

    const int sub  = lane >> 3;
    const int rsel = (lane & 7) + (sub & 1) * 8;

    auto load_stage = [&](int st, int kt) {
        const uint32_t sbst = sbase + (uint32_t)st * 32768u;   // bytes
#pragma unroll
        for (int i = tid; i < 512; i += 256) {                  // A: 128r x 4ch
            int r = i >> 2, cc = i & 3;
            uint32_t d = sbst + (uint32_t)(r * 32 + ((cc ^ ((r >> 1) & 3)) * 8)) * 2;
            const size_t go = (size_t)(bm + r) * K + kt + cc * 8;
            cpa16(d,        g.Ahi + go);
            cpa16(d + 8192, g.Alo + go);
        }
#pragma unroll
        for (int i = tid; i < 512; i += 256) {                  // W: 32k x 16ch
            int kr = i >> 4, cc = i & 15;
            uint32_t d = sbst + 16384u +
                         (uint32_t)(kr * 128 + ((cc ^ (kr & 7)) * 8)) * 2;
            const size_t go = (size_t)(kt + kr) * N + bn + cc * 8;
            cpa16(d,        g.Whi + go);
            cpa16(d + 8192, g.Wlo + go);
        }
    };

    load_stage(0, 0);  CP_COMMIT();
    load_stage(1, 32); CP_COMMIT();

    for (int it = 0; it < niter; it++) {
        CP_WAIT1();
        __syncthreads();
        if (it + 2 < niter) load_stage((it + 2) % 3, (it + 2) * 32);
        CP_COMMIT();

        const uint32_t sst = sbase + (uint32_t)(it % 3) * 32768u;
#pragma unroll
        for (int ks = 0; ks < 2; ks++) {
            uint32_t ah[2][4], al[2][4];
#pragma unroll
            for (int mt = 0; mt < 2; mt++) {
                const int row = wm + mt * 16 + rsel;
                const int ch  = (ks * 2 + (sub >> 1)) ^ ((row >> 1) & 3);
                const uint32_t ad = sst + (uint32_t)(row * 32 + ch * 8) * 2;
                LDSM4(ah[mt], ad);
                LDSM4(al[mt], ad + 8192);
            }
            const int kin = ks * 16 + rsel;
#pragma unroll
            for (int half = 0; half < 2; half++) {
                uint32_t bh[4][2], bl[4][2];
#pragma unroll
                for (int p = 0; p < 2; p++) {
                    const int nt0 = half * 4 + p * 2 + (sub >> 1);
                    const int ch  = ((wn >> 3) + nt0) ^ (kin & 7);
                    const uint32_t ad = sst + 16384u +
                        (uint32_t)(kin * 128 + ch * 8) * 2;
                    uint32_t t0[4], t1[4];
                    LDSM4T(t0, ad);
                    LDSM4T(t1, ad + 8192);
                    bh[p * 2][0] = t0[0]; bh[p * 2][1] = t0[1];
                    bh[p * 2 + 1][0] = t0[2]; bh[p * 2 + 1][1] = t0[3];
                    bl[p * 2][0] = t1[0]; bl[p * 2][1] = t1[1];
                    bl[p * 2 + 1][0] = t1[2]; bl[p * 2 + 1][1] = t1[3];
                }
#pragma unroll
                for (int mt = 0; mt < 2; mt++)
#pragma unroll
                    for (int ln = 0; ln < 4; ln++) {
                        float* acc = c[mt][half * 4 + ln];
                        mma16816(acc, ah[mt], bh[ln]);
                        mma16816(acc, ah[mt], bl[ln]);
                        mma16816(acc, al[mt], bh[ln]);
                    }
            }
        }
    }

    const int gg = lane >> 2, tg = lane & 3;
#pragma unroll
    for (int mt = 0; mt < 2; mt++)
#pragma unroll
        for (int nt = 0; nt < 8; nt++) {
            const int col = bn + wn + nt * 8 + 2 * tg;
            const float2 bb = *(const float2*)(g.bias + col);
            const float bx = bb.x * g.bscale, by = bb.y * g.bscale;
            const int r0 = bm + wm + mt * 16 + gg;
            const float v00 = c[mt][nt][0] + bx, v01 = c[mt][nt][1] + by;
            const float v10 = c[mt][nt][2] + bx, v11 = c[mt][nt][3] + by;
            if (SPLIT) {
                __nv_bfloat162 h0 = __floats2bfloat162_rn(v00, v01);
                __nv_bfloat162 l0 = __floats2bfloat162_rn(
                    v00 - __bfloat162float(h0.x), v01 - __bfloat162float(h0.y));
                __nv_bfloat162 h1 = __floats2bfloat162_rn(v10, v11);
                __nv_bfloat162 l1 = __floats2bfloat162_rn(
                    v10 - __bfloat162float(h1.x), v11 - __bfloat162float(h1.y));
                *(__nv_bfloat162*)(g.Chi + (size_t)r0 * N + col)       = h0;
                *(__nv_bfloat162*)(g.Clo + (size_t)r0 * N + col)       = l0;
                *(__nv_bfloat162*)(g.Chi + (size_t)(r0 + 8) * N + col) = h1;
                *(__nv_bfloat162*)(g.Clo + (size_t)(r0 + 8) * N + col) = l1;
            } else {
                float2 o0, o1;
                o0.x = v00; o0.y = v01; o1.x = v10; o1.y = v11;
                *(float2*)(g.Cf + (size_t)r0 * N + col)       = o0;
                *(float2*)(g.Cf + (size_t)(r0 + 8) * N + col) = o1;
            }
        }
}

// ---------------------------------------------------------------------------
// Tensorized MQA flash attention, 128 q-rows/CTA, 8 warps, cp.async 2-stage KV.
// smem bytes: Qhi 0, Qlo 32768; stage s at 65536+s*65536:
//   Khi +0, Klo +16384, Vhi +32768, Vlo +49152. Total 192KB.
// Output: bf16 hi/lo (feeds O-projection GEMM).
// ---------------------------------------------------------------------------
__global__ void __launch_bounds__(256, 1)
mqa_flash_tc(const __nv_bfloat16* __restrict__ Qhi, const __nv_bfloat16* __restrict__ Qlo,
             const __nv_bfloat16* __restrict__ Khi, const __nv_bfloat16* __restrict__ Klo,
             const __nv_bfloat16* __restrict__ Vhi, const __nv_bfloat16* __restrict__ Vlo,
             __nv_bfloat16* __restrict__ AOhi, __nv_bfloat16* __restrict__ AOlo)
{
    extern __shared__ __align__(16) __nv_bfloat16 sm[];
    const uint32_t sb = (uint32_t)__cvta_generic_to_shared(sm);
    const int tid = threadIdx.x, lane = tid & 31, wid = tid >> 5;
    const int b = blockIdx.z, h = blockIdx.y, q0 = blockIdx.x * 128;
    const int wm = wid * 16;
    const size_t kvbase = (size_t)b * SEQ * DHEAD;
    const __nv_bfloat16* kvsrc[4] = {Khi + kvbase, Klo + kvbase,
                                     Vhi + kvbase, Vlo + kvbase};

    auto load_kv = [&](int st, int j0) {
        const uint32_t stb = sb + 65536u + (uint32_t)st * 65536u;
#pragma unroll
        for (int t4 = 0; t4 < 4; t4++) {
            const __nv_bfloat16* src = kvsrc[t4] + (size_t)j0 * DHEAD;
            const uint32_t dst0 = stb + (uint32_t)t4 * 16384u;
#pragma unroll
            for (int i = tid; i < 1024; i += 256) {
                int r = i >> 4, cc = i & 15;
                cpa16(dst0 + (uint32_t)(r * 128 + ((cc ^ (r & 7)) * 8)) * 2,
                      src + r * 128 + cc * 8);
            }
        }
    };

    load_kv(0, 0);  CP_COMMIT();
    load_kv(1, 64); CP_COMMIT();

    // Q tile 128x128 hi/lo (regular loads, overlap with cp.async above)
    {
        const size_t qb = ((size_t)b * SEQ + q0) * DIM + h * DHEAD;
#pragma unroll
        for (int i = tid; i < 2048; i += 256) {
            int r = i >> 4, cc = i & 15;
            int d = r * 128 + ((cc ^ (r & 7)) * 8);
            const size_t gs = qb + (size_t)r * DIM + cc * 8;
            *(uint4*)(sm + d)         = *(const uint4*)(Qhi + gs);
            *(uint4*)(sm + 16384 + d) = *(const uint4*)(Qlo + gs);
        }
    }
    CP_WAIT1();
    __syncthreads();

    // Q-hi fragments pinned in registers; Q-lo reloaded per tile (reg pressure)
    uint32_t qfh[8][4], qladdr[8];
    {
        const int r = wm + (lane & 7) + ((lane >> 3) & 1) * 8;
#pragma unroll
        for (int d = 0; d < 8; d++) {
            int cc = 2 * d + (lane >> 4);
            uint32_t ad = sb + (uint32_t)(r * 128 + ((cc ^ (r & 7)) * 8)) * 2;
            LDSM4(qfh[d], ad);
            qladdr[d] = ad + 32768u;
        }
    }

    float m0 = -1e30f, m1 = -1e30f, sl0 = 0.f, sl1 = 0.f;
    float o[16][4];
#pragma unroll
    for (int nt = 0; nt < 16; nt++)
#pragma unroll
        for (int q = 0; q < 4; q++) o[nt][q] = 0.f;

    for (int it = 0; it < 32; it++) {
        const uint32_t stb = sb + 65536u + (uint32_t)(it & 1) * 65536u;

        // ---- S = Q K^T (bf16x3) ----
        float s[8][4];
#pragma unroll
        for (int j = 0; j < 8; j++)
#pragma unroll
            for (int q = 0; q < 4; q++) s[j][q] = 0.f;
        {
            const int rr = (lane & 7) + ((lane >> 3) & 1) * 8;
#pragma unroll
            for (int d = 0; d < 8; d++) {
                int cc = 2 * d + (lane >> 4);
                uint32_t ql[4];
                LDSM4(ql, qladdr[d]);
#pragma unroll
                for (int jb = 0; jb < 4; jb++) {
                    int r = jb * 16 + rr;
                    uint32_t ad = stb + (uint32_t)(r * 128 + ((cc ^ (r & 7)) * 8)) * 2;
                    uint32_t kh[4], kl[4];
                    LDSM4(kh, ad);
                    LDSM4(kl, ad + 16384u);
                    uint32_t b0h[2] = {kh[0], kh[2]}, b1h[2] = {kh[1], kh[3]};
                    uint32_t b0l[2] = {kl[0], kl[2]}, b1l[2] = {kl[1], kl[3]};
                    mma16816(s[2 * jb],     qfh[d], b0h);
                    mma16816(s[2 * jb],     qfh[d], b0l);
                    mma16816(s[2 * jb],     ql,     b0h);
                    mma16816(s[2 * jb + 1], qfh[d], b1h);
                    mma16816(s[2 * jb + 1], qfh[d], b1l);
                    mma16816(s[2 * jb + 1], ql,     b1h);
                }
            }
        }

        // ---- online softmax (log2 domain) ----
        float rm0 = s[0][0], rm1 = s[0][2];
#pragma unroll
        for (int j = 0; j < 8; j++) {
            rm0 = fmaxf(rm0, fmaxf(s[j][0], s[j][1]));
            rm1 = fmaxf(rm1, fmaxf(s[j][2], s[j][3]));
        }
        rm0 = fmaxf(rm0, __shfl_xor_sync(0xffffffffu, rm0, 1));
        rm0 = fmaxf(rm0, __shfl_xor_sync(0xffffffffu, rm0, 2));
        rm1 = fmaxf(rm1, __shfl_xor_sync(0xffffffffu, rm1, 1));
        rm1 = fmaxf(rm1, __shfl_xor_sync(0xffffffffu, rm1, 2));
        const float mn0 = fmaxf(m0, rm0), mn1 = fmaxf(m1, rm1);
        const float a0 = exp2_fast(m0 - mn0), a1 = exp2_fast(m1 - mn1);
        m0 = mn0; m1 = mn1;
        float rs0 = 0.f, rs1 = 0.f;
#pragma unroll
        for (int j = 0; j < 8; j++) {
            float p0 = exp2_fast(s[j][0] - mn0); s[j][0] = p0;
            float p1 = exp2_fast(s[j][1] - mn0); s[j][1] = p1;
            float p2 = exp2_fast(s[j][2] - mn1); s[j][2] = p2;
            float p3 = exp2_fast(s[j][3] - mn1); s[j][3] = p3;
            rs0 += p0 + p1; rs1 += p2 + p3;
        }
        rs0 += __shfl_xor_sync(0xffffffffu, rs0, 1);
        rs0 += __shfl_xor_sync(0xffffffffu, rs0, 2);
        rs1 += __shfl_xor_sync(0xffffffffu, rs1, 1);
        rs1 += __shfl_xor_sync(0xffffffffu, rs1, 2);
        sl0 = sl0 * a0 + rs0;
        sl1 = sl1 * a1 + rs1;
#pragma unroll
        for (int nt = 0; nt < 16; nt++) {
            o[nt][0] *= a0; o[nt][1] *= a0; o[nt][2] *= a1; o[nt][3] *= a1;
        }

        // ---- P fragments (C-frag -> A-frag remap, hi/lo split) ----
        uint32_t ph[4][4], pl[4][4];
#pragma unroll
        for (int jp = 0; jp < 4; jp++)
#pragma unroll
            for (int idx = 0; idx < 4; idx++) {
                float x0 = s[2 * jp + (idx >> 1)][(idx & 1) * 2 + 0];
                float x1 = s[2 * jp + (idx >> 1)][(idx & 1) * 2 + 1];
                __nv_bfloat162 hh = __floats2bfloat162_rn(x0, x1);
                __nv_bfloat162 ll = __floats2bfloat162_rn(
                    x0 - __bfloat162float(hh.x), x1 - __bfloat162float(hh.y));
                ph[jp][idx] = *(uint32_t*)&hh;
                pl[jp][idx] = *(uint32_t*)&ll;
            }

        // ---- O += P V (bf16x3) ----
        {
            const int rv = (lane & 7) + ((lane >> 3) & 1) * 8;
#pragma unroll
            for (int g2 = 0; g2 < 8; g2++) {
                int cc = 2 * g2 + (lane >> 4);
#pragma unroll
                for (int jp = 0; jp < 4; jp++) {
                    int r = jp * 16 + rv;
                    uint32_t ad = stb + 32768u +
                        (uint32_t)(r * 128 + ((cc ^ (r & 7)) * 8)) * 2;
                    uint32_t vh[4], vl[4];
                    LDSM4T(vh, ad);
                    LDSM4T(vl, ad + 16384u);
                    uint32_t b0h[2] = {vh[0], vh[1]}, b1h[2] = {vh[2], vh[3]};
                    uint32_t b0l[2] = {vl[0], vl[1]}, b1l[2] = {vl[2], vl[3]};
                    mma16816(o[2 * g2],     ph[jp], b0h);
                    mma16816(o[2 * g2],     ph[jp], b0l);
                    mma16816(o[2 * g2],     pl[jp], b0h);
                    mma16816(o[2 * g2 + 1], ph[jp], b1h);
                    mma16816(o[2 * g2 + 1], ph[jp], b1l);
                    mma16816(o[2 * g2 + 1], pl[jp], b1h);
                }
            }
        }

        // ---- pipeline bookkeeping ----
        __syncthreads();                        // all warps done with buf it&1
        if (it + 2 < 32) load_kv(it & 1, (it + 2) * 64);
        CP_COMMIT();
        CP_WAIT1();                             // stage it+1 landed
        __syncthreads();
    }

    // ---- epilogue: normalize + bf16 hi/lo split store ----
    const float i0 = 1.0f / sl0, i1 = 1.0f / sl1;
    const int gg = lane >> 2, t = lane & 3;
    const size_t ob = ((size_t)b * SEQ + q0 + wm) * DIM + h * DHEAD;
#pragma unroll
    for (int nt = 0; nt < 16; nt++) {
        const int col = nt * 8 + 2 * t;
        const float a0 = o[nt][0] * i0, a1 = o[nt][1] * i0;
        const float c0 = o[nt][2] * i1, c1 = o[nt][3] * i1;
        __nv_bfloat162 h0 = __floats2bfloat162_rn(a0, a1);
        __nv_bfloat162 l0 = __floats2bfloat162_rn(a0 - __bfloat162float(h0.x),
                                                  a1 - __bfloat162float(h0.y));
        __nv_bfloat162 h1 = __floats2bfloat162_rn(c0, c1);
        __nv_bfloat162 l1 = __floats2bfloat162_rn(c0 - __bfloat162float(h1.x),
                                                  c1 - __bfloat162float(h1.y));
        *(__nv_bfloat162*)(AOhi + ob + (size_t)gg * DIM + col)       = h0;
        *(__nv_bfloat162*)(AOlo + ob + (size_t)gg * DIM + col)       = l0;
        *(__nv_bfloat162*)(AOhi + ob + (size_t)(gg + 8) * DIM + col) = h1;
        *(__nv_bfloat162*)(AOlo + ob + (size_t)(gg + 8) * DIM + col) = l1;
    }
}

// ---------------------------------------------------------------------------
extern "C" void kernel_launch(void* const* d_in, const int* in_sizes, int n_in,
                              void* d_out, int out_size)
{
    const float* q  = (const float*)d_in[0];
    const float* k  = (const float*)d_in[1];
    const float* v  = (const float*)d_in[2];
    const float* Wq = (const float*)d_in[3];
    const float* bq = (const float*)d_in[4];
    const float* Wk = (const float*)d_in[5];
    const float* bk = (const float*)d_in[6];
    const float* Wv = (const float*)d_in[7];
    const float* bv = (const float*)d_in[8];
    const float* Wo = (const float*)d_in[9];
    const float* bo = (const float*)d_in[10];
    float* out = (float*)d_out;

    __nv_bfloat16 *iq_h, *iq_l, *ik_h, *ik_l, *iv_h, *iv_l;
    __nv_bfloat16 *wq_h, *wq_l, *wo_h, *wo_l, *wk_h, *wk_l, *wv_h, *wv_l;
    __nv_bfloat16 *q_h, *q_l, *k_h, *k_l, *v_h, *v_l, *ao_h, *ao_l;
    cudaGetSymbolAddress((void**)&iq_h, d_iq_h); cudaGetSymbolAddress((void**)&iq_l, d_iq_l);
    cudaGetSymbolAddress((void**)&ik_h, d_ik_h); cudaGetSymbolAddress((void**)&ik_l, d_ik_l);
    cudaGetSymbolAddress((void**)&iv_h, d_iv_h); cudaGetSymbolAddress((void**)&iv_l, d_iv_l);
    cudaGetSymbolAddress((void**)&wq_h, d_wq_h); cudaGetSymbolAddress((void**)&wq_l, d_wq_l);
    cudaGetSymbolAddress((void**)&wo_h, d_wo_h); cudaGetSymbolAddress((void**)&wo_l, d_wo_l);
    cudaGetSymbolAddress((void**)&wk_h, d_wk_h); cudaGetSymbolAddress((void**)&wk_l, d_wk_l);
    cudaGetSymbolAddress((void**)&wv_h, d_wv_h); cudaGetSymbolAddress((void**)&wv_l, d_wv_l);
    cudaGetSymbolAddress((void**)&q_h,  d_q_h);  cudaGetSymbolAddress((void**)&q_l,  d_q_l);
    cudaGetSymbolAddress((void**)&k_h,  d_k_h);  cudaGetSymbolAddress((void**)&k_l,  d_k_l);
    cudaGetSymbolAddress((void**)&v_h,  d_v_h);  cudaGetSymbolAddress((void**)&v_l,  d_v_l);
    cudaGetSymbolAddress((void**)&ao_h, d_ao_h); cudaGetSymbolAddress((void**)&ao_l, d_ao_l);

    const int M = BATCH * SEQ;                     // 8192
    const float SCL = 0.1275174414f;               // 1/sqrt(128) * log2(e)

    const int gsmem = 3 * 16384 * 2;               // 96 KB
    cudaFuncSetAttribute(gemm_bf16x3<true>,
                         cudaFuncAttributeMaxDynamicSharedMemorySize, gsmem);
    cudaFuncSetAttribute(gemm_bf16x3<false>,
                         cudaFuncAttributeMaxDynamicSharedMemorySize, gsmem);
    const int asmem = 192 * 1024;
    cudaFuncSetAttribute(mqa_flash_tc,
                         cudaFuncAttributeMaxDynamicSharedMemorySize, asmem);

    // ---- pre-split inputs and weights ----
    const int nact4 = M * DIM / 4;                 // 4.19M
    split_scale<<<nact4 / 256, 256>>>((const float4*)q, (uint2*)iq_h, (uint2*)iq_l, 1.f, nact4);
    split_scale<<<nact4 / 256, 256>>>((const float4*)k, (uint2*)ik_h, (uint2*)ik_l, 1.f, nact4);
    split_scale<<<nact4 / 256, 256>>>((const float4*)v, (uint2*)iv_h, (uint2*)iv_l, 1.f, nact4);
    const int nw4 = DIM * DIM / 4;
    split_scale<<<nw4 / 256, 256>>>((const float4*)Wq, (uint2*)wq_h, (uint2*)wq_l, SCL, nw4);
    split_scale<<<nw4 / 256, 256>>>((const float4*)Wo, (uint2*)wo_h, (uint2*)wo_l, 1.f, nw4);
    const int nwk4 = DIM * DHEAD / 4;
    split_scale<<<nwk4 / 256, 256>>>((const float4*)Wk, (uint2*)wk_h, (uint2*)wk_l, 1.f, nwk4);
    split_scale<<<nwk4 / 256, 256>>>((const float4*)Wv, (uint2*)wv_h, (uint2*)wv_l, 1.f, nwk4);

    // ---- Q projection (scale folded into Wq/bq), split output ----
    GemmArgs qa;
    qa.op[0] = {iq_h, iq_l, wq_h, wq_l, bq, SCL, nullptr, q_h, q_l};
    qa.op[1] = qa.op[0];
    gemm_bf16x3<true><<<dim3(DIM / 128, M / 128, 1), 256, gsmem>>>(qa, M, DIM, DIM);

    // ---- K and V projections fused in one launch (grid.z = 2) ----
    GemmArgs kva;
    kva.op[0] = {ik_h, ik_l, wk_h, wk_l, bk, 1.f, nullptr, k_h, k_l};
    kva.op[1] = {iv_h, iv_l, wv_h, wv_l, bv, 1.f, nullptr, v_h, v_l};
    gemm_bf16x3<true><<<dim3(1, M / 128, 2), 256, gsmem>>>(kva, M, DHEAD, DIM);

    // ---- attention (split output feeds O-proj) ----
    mqa_flash_tc<<<dim3(SEQ / 128, HEADS, BATCH), 256, asmem>>>(
        q_h, q_l, k_h, k_l, v_h, v_l, ao_h, ao_l);

    // ---- O projection, fp32 output ----
    GemmArgs oa;
    oa.op[0] = {ao_h, ao_l, wo_h, wo_l, bo, 1.f, out, nullptr, nullptr};
    oa.op[1] = oa.op[0];
    gemm_bf16x3<false><<<dim3(DIM / 128, M / 128, 1), 256, gsmem>>>(oa, M, DIM, DIM);
}